// round 17
// baseline (speedup 1.0000x reference)
#include <cuda_runtime.h>
#include <cuda_fp16.h>
#include <math.h>
#include <stdint.h>

// ---------------------------------------------------------------------------
// CLIP ViT-B/16 forward. Round 16: GEMM block tile 128x256 (warp tile 64x64),
// halving LDSM-per-HMMA. 3-stage cp.async, 1 CTA/SM. Rest = verified R15.
// ---------------------------------------------------------------------------

#define BB      32
#define NTOK    197
#define NPAT    196
#define DD      768
#define DEPTH   12
#define NH      12
#define DH      64
#define MLPD    3072
#define PROJD   512
#define NCLS    1000
#define MROWS   (BB*NTOK)          // 6304
#define PROWS   (BB*NPAT)          // 6272

// fp32 buffers
__device__ __align__(128) float  g_x   [MROWS*DD];
__device__ __align__(128) float  g_pe  [PROWS*DD];
__device__ __align__(128) float  g_cls [BB*DD];
__device__ __align__(128) float  g_cr  [BB*DD];
__device__ __align__(128) float  g_cx2 [BB*DD];
__device__ __align__(128) float  g_cx3 [BB*DD];
__device__ __align__(128) float  g_z   [BB*PROJD];
// fp16 buffers
__device__ __align__(128) __half g_qkv [MROWS*3*DD];
__device__ __align__(128) __half g_h   [MROWS*DD];
__device__ __align__(128) __half g_o   [MROWS*DD];
__device__ __align__(128) __half g_mlp [MROWS*MLPD];
__device__ __align__(128) __half g_pat [PROWS*DD];
__device__ __align__(128) __half g_ca  [BB*DD];
// fp16 weights
__device__ __align__(128) __half g_wconv [DD*DD];
__device__ __align__(128) __half g_wqkv  [DEPTH*3*DD*DD];
__device__ __align__(128) __half g_wproj [DEPTH*DD*DD];
__device__ __align__(128) __half g_wfc   [DEPTH*MLPD*DD];
__device__ __align__(128) __half g_wcpr  [DEPTH*DD*MLPD];

// ---------------------------------------------------------------------------
// merged fp32 -> fp16 weight conversion
// ---------------------------------------------------------------------------
#define F2H_C0 (DD*DD/8)
#define F2H_C1 (F2H_C0 + DEPTH*3*DD*DD/8)
#define F2H_C2 (F2H_C1 + DEPTH*DD*DD/8)
#define F2H_C3 (F2H_C2 + DEPTH*MLPD*DD/8)
#define F2H_C4 (F2H_C3 + DEPTH*DD*MLPD/8)

__global__ void f2h_all_kernel(const float* __restrict__ s0, __half* d0,
                               const float* __restrict__ s1, __half* d1,
                               const float* __restrict__ s2, __half* d2,
                               const float* __restrict__ s3, __half* d3,
                               const float* __restrict__ s4, __half* d4) {
    int i = blockIdx.x * 256 + threadIdx.x;
    if (i >= F2H_C4) return;
    const float* src; __half* dst; int off;
    if      (i < F2H_C0) { src = s0; dst = d0; off = i; }
    else if (i < F2H_C1) { src = s1; dst = d1; off = i - F2H_C0; }
    else if (i < F2H_C2) { src = s2; dst = d2; off = i - F2H_C1; }
    else if (i < F2H_C3) { src = s3; dst = d3; off = i - F2H_C2; }
    else                 { src = s4; dst = d4; off = i - F2H_C3; }
    const float4* p = (const float4*)src + (size_t)off*2;
    float4 a = p[0], b = p[1];
    __half2 h0 = __floats2half2_rn(a.x, a.y);
    __half2 h1 = __floats2half2_rn(a.z, a.w);
    __half2 h2 = __floats2half2_rn(b.x, b.y);
    __half2 h3 = __floats2half2_rn(b.z, b.w);
    uint4 v;
    v.x = *(uint32_t*)&h0; v.y = *(uint32_t*)&h1;
    v.z = *(uint32_t*)&h2; v.w = *(uint32_t*)&h3;
    ((uint4*)dst)[off] = v;
}

// ---------------------------------------------------------------------------
// im2col
// ---------------------------------------------------------------------------
__global__ void im2col_kernel(const float* __restrict__ x) {
    int idx = blockIdx.x * 256 + threadIdx.x;
    if (idx >= PROWS * DD) return;
    int k = idx % DD;
    int m = idx / DD;
    int b = m / NPAT, p = m % NPAT;
    int ph = p / 14, pw = p % 14;
    int c = k >> 8, r = (k >> 4) & 15, col = k & 15;
    g_pat[idx] = __float2half_rn(x[(((long)(b*3 + c)*224 + ph*16 + r)*224) + pw*16 + col]);
}

// ---------------------------------------------------------------------------
// fused assemble + ln_pre
// ---------------------------------------------------------------------------
__global__ void assemble_ln_kernel(const float* __restrict__ pe,
                                   const float* __restrict__ cls_tok,
                                   const float* __restrict__ pos,
                                   const float* __restrict__ gam,
                                   const float* __restrict__ bet,
                                   float* __restrict__ out) {
    __shared__ float red[16];
    int row = blockIdx.x, tid = threadIdx.x;
    int b = row / NTOK, n = row % NTOK;
    float v0, v1, v2;
    if (n == 0) {
        v0 = cls_tok[tid      ] + pos[tid      ];
        v1 = cls_tok[tid + 256] + pos[tid + 256];
        v2 = cls_tok[tid + 512] + pos[tid + 512];
    } else {
        const float* per = pe + ((size_t)b*NPAT + (n-1))*DD;
        const float* por = pos + (size_t)n*DD;
        v0 = per[tid      ] + por[tid      ];
        v1 = per[tid + 256] + por[tid + 256];
        v2 = per[tid + 512] + por[tid + 512];
    }
    float s = v0 + v1 + v2;
    #pragma unroll
    for (int o = 16; o; o >>= 1) s += __shfl_xor_sync(0xffffffffu, s, o);
    if ((tid & 31) == 0) red[tid >> 5] = s;
    __syncthreads();
    float tot = red[0]+red[1]+red[2]+red[3]+red[4]+red[5]+red[6]+red[7];
    float mean = tot * (1.0f / 768.0f);
    float d0 = v0 - mean, d1 = v1 - mean, d2 = v2 - mean;
    float q = d0*d0 + d1*d1 + d2*d2;
    #pragma unroll
    for (int o = 16; o; o >>= 1) q += __shfl_xor_sync(0xffffffffu, q, o);
    if ((tid & 31) == 0) red[8 + (tid >> 5)] = q;
    __syncthreads();
    float var = (red[8]+red[9]+red[10]+red[11]+red[12]+red[13]+red[14]+red[15]) * (1.0f/768.0f);
    float rs = rsqrtf(var + 1e-5f);
    float* orow = out + (size_t)row * DD;
    orow[tid      ] = d0 * rs * gam[tid      ] + bet[tid      ];
    orow[tid + 256] = d1 * rs * gam[tid + 256] + bet[tid + 256];
    orow[tid + 512] = d2 * rs * gam[tid + 512] + bet[tid + 512];
}

// ---------------------------------------------------------------------------
// LayerNorm over 768: warp-per-row, no barriers. 256 threads = 8 rows/block.
// ---------------------------------------------------------------------------
template<typename OutT>
__global__ void ln_warp(const float* __restrict__ in, OutT* __restrict__ out,
                        const float* __restrict__ gam, const float* __restrict__ bet,
                        long in_stride, long out_stride) {
    int warp = threadIdx.x >> 5, lane = threadIdx.x & 31;
    int row = blockIdx.x * 8 + warp;
    const float4* xr = (const float4*)(in + (size_t)row * in_stride);
    float4 v[6];
    float s = 0.f;
    #pragma unroll
    for (int j = 0; j < 6; j++) {
        v[j] = xr[lane + 32*j];
        s += (v[j].x + v[j].y) + (v[j].z + v[j].w);
    }
    #pragma unroll
    for (int o = 16; o; o >>= 1) s += __shfl_xor_sync(0xffffffffu, s, o);
    float mean = s * (1.0f/768.0f);
    float q = 0.f;
    #pragma unroll
    for (int j = 0; j < 6; j++) {
        v[j].x -= mean; v[j].y -= mean; v[j].z -= mean; v[j].w -= mean;
        q += (v[j].x*v[j].x + v[j].y*v[j].y) + (v[j].z*v[j].z + v[j].w*v[j].w);
    }
    #pragma unroll
    for (int o = 16; o; o >>= 1) q += __shfl_xor_sync(0xffffffffu, q, o);
    float rs = rsqrtf(q * (1.0f/768.0f) + 1e-5f);
    const float4* g4 = (const float4*)gam;
    const float4* b4 = (const float4*)bet;
    if (sizeof(OutT) == 2) {
        __half* orow = (__half*)out + (size_t)row * out_stride;
        #pragma unroll
        for (int j = 0; j < 6; j++) {
            float4 g = g4[lane + 32*j], bb = b4[lane + 32*j];
            __half2 h0 = __floats2half2_rn(v[j].x*rs*g.x + bb.x, v[j].y*rs*g.y + bb.y);
            __half2 h1 = __floats2half2_rn(v[j].z*rs*g.z + bb.z, v[j].w*rs*g.w + bb.w);
            uint2 u; u.x = *(uint32_t*)&h0; u.y = *(uint32_t*)&h1;
            *(uint2*)&orow[(lane + 32*j)*4] = u;
        }
    } else {
        float* orow = (float*)out + (size_t)row * out_stride;
        #pragma unroll
        for (int j = 0; j < 6; j++) {
            float4 g = g4[lane + 32*j], bb = b4[lane + 32*j];
            float4 o4;
            o4.x = v[j].x*rs*g.x + bb.x; o4.y = v[j].y*rs*g.y + bb.y;
            o4.z = v[j].z*rs*g.z + bb.z; o4.w = v[j].w*rs*g.w + bb.w;
            ((float4*)orow)[lane + 32*j] = o4;
        }
    }
}

__device__ __forceinline__ float gelu_f(float v) {
    return 0.5f * v * (1.0f + erff(v * 0.70710678118654752f));
}

// ---------------------------------------------------------------------------
// gather cls rows
// ---------------------------------------------------------------------------
__global__ void gather_cls_kernel(const __half* __restrict__ go,
                                  const float* __restrict__ gx,
                                  __half* __restrict__ a16,
                                  float* __restrict__ r32) {
    int idx = blockIdx.x * 256 + threadIdx.x;
    if (idx >= BB*DD) return;
    int b = idx / DD, d = idx % DD;
    size_t src = (size_t)b * NTOK * DD + d;
    a16[idx] = go[src];
    r32[idx] = gx[src];
}

// ---------------------------------------------------------------------------
// common PTX helpers
// ---------------------------------------------------------------------------
__device__ __forceinline__ uint32_t smem_u32(const void* p) {
    uint32_t a;
    asm("{ .reg .u64 t; cvta.to.shared.u64 t, %1; cvt.u32.u64 %0, t; }" : "=r"(a) : "l"(p));
    return a;
}

#define LDSM_X4(r0,r1,r2,r3,addr) \
    asm volatile("ldmatrix.sync.aligned.m8n8.x4.shared.b16 {%0,%1,%2,%3}, [%4];" \
                 : "=r"(r0), "=r"(r1), "=r"(r2), "=r"(r3) : "r"(addr))

#define HMMA16816(d, a0,a1,a2,a3, b0,b1) \
    asm volatile("mma.sync.aligned.m16n8k16.row.col.f32.f16.f16.f32 " \
                 "{%0,%1,%2,%3}, {%4,%5,%6,%7}, {%8,%9}, {%0,%1,%2,%3};" \
                 : "+f"((d)[0]), "+f"((d)[1]), "+f"((d)[2]), "+f"((d)[3]) \
                 : "r"(a0), "r"(a1), "r"(a2), "r"(a3), "r"(b0), "r"(b1))

__device__ __forceinline__ void cp16(uint32_t saddr, const void* gaddr) {
    asm volatile("cp.async.cg.shared.global [%0], [%1], 16;" :: "r"(saddr), "l"(gaddr));
}
__device__ __forceinline__ void cp16z(uint32_t saddr, const void* gaddr, int sz) {
    asm volatile("cp.async.cg.shared.global [%0], [%1], 16, %2;" :: "r"(saddr), "l"(gaddr), "r"(sz));
}
#define CP_COMMIT() asm volatile("cp.async.commit_group;" ::: "memory")
#define CP_WAIT1()  asm volatile("cp.async.wait_group 1;" ::: "memory")

// ---------------------------------------------------------------------------
// fp16 tensor-core NT GEMM: block 128x256, warp tile 64x64, BK=64, 3-stage
// cp.async, 1 CTA/SM. Tail tile (rows floor(M/128)*128..M, <=32 rows) = LAST
// y-block. Requires N % 256 == 0, K % 64 == 0.
// ---------------------------------------------------------------------------
#define HPITCH  144
#define HBOFF   (128*HPITCH)              // B region offset in a stage
#define HSTAGE  (HBOFF + 256*HPITCH)      // 55296
#define GH_SMEM (3*HSTAGE)                // 165888

template<typename OutT, bool GELU, bool RES>
__global__ __launch_bounds__(256, 1)
void gemm_h(const __half* __restrict__ A, const __half* __restrict__ W,
            const float* __restrict__ bias, const float* __restrict__ Rs,
            OutT* __restrict__ Cp, int M, int N, int K) {
    extern __shared__ uint8_t smem[];
    const uint32_t sb = smem_u32(smem);
    const int tid = threadIdx.x, lane = tid & 31, warp = tid >> 5;
    const int wm = warp >> 2, wn = warp & 3;         // 2 x 4 warps, tile 64x64
    const int by = blockIdx.y;
    const bool tail = (by == gridDim.y - 1);
    const int m0 = tail ? ((M >> 7) << 7) : (by << 7);
    const int n0 = blockIdx.x * 256;

    float acc[4][8][4];
    #pragma unroll
    for (int i=0;i<4;i++)
      #pragma unroll
      for (int j=0;j<8;j++)
        #pragma unroll
        for (int f=0;f<4;f++) acc[i][j][f]=0.f;

    const int T = K >> 6;

    const int row0 = tid >> 3, ch = tid & 7;
    int    szA[4];
    size_t offA[4];
    #pragma unroll
    for (int it = 0; it < 4; it++) {
        int r = m0 + row0 + it*32;
        szA[it]  = (r < M) ? 16 : 0;
        offA[it] = szA[it] ? ((size_t)r * K + ch*8) : 0;
    }
    const __half* Bbase = W + (size_t)(n0 + row0) * K + ch*8;
    const uint32_t sbase = sb + (uint32_t)row0 * HPITCH + ch*16;

    auto issue_stage = [&](int t, int s) {
        if (t < T) {
            uint32_t so = sbase + (uint32_t)s * HSTAGE;
            int ko = t * 64;
            #pragma unroll
            for (int it = 0; it < 4; it++)
                cp16z(so + it*(32*HPITCH), A + offA[it] + (szA[it] ? ko : 0), szA[it]);
            #pragma unroll
            for (int it = 0; it < 8; it++)
                cp16(so + HBOFF + it*(32*HPITCH), Bbase + (size_t)it*32*K + ko);
        }
        CP_COMMIT();
    };

    const uint32_t aoff = (uint32_t)(wm*64 + (lane & 15)) * HPITCH + (lane >> 4) * 16;
    const uint32_t boff = HBOFF
                        + (uint32_t)(wn*64 + (lane & 7) + ((lane >> 4) << 3)) * HPITCH
                        + ((lane >> 3) & 1) * 16;

    issue_stage(0, 0);
    issue_stage(1, 1);

    int cur = 0, nxt = 2;
    for (int t = 0; t < T; t++) {
        CP_WAIT1();
        __syncthreads();
        issue_stage(t + 2, nxt);
        nxt = (nxt == 2) ? 0 : nxt + 1;
        const uint32_t stb = sb + (uint32_t)cur * HSTAGE;
        cur = (cur == 2) ? 0 : cur + 1;

        if (tail) {
            if (wm == 0) {
                #pragma unroll
                for (int kc = 0; kc < 4; kc++) {
                    uint32_t af[2][4];
                    #pragma unroll
                    for (int mt = 0; mt < 2; mt++) {
                        uint32_t addr = stb + aoff + mt*16*HPITCH + kc*32;
                        LDSM_X4(af[mt][0], af[mt][1], af[mt][2], af[mt][3], addr);
                    }
                    uint32_t bf[4][4];
                    #pragma unroll
                    for (int pr = 0; pr < 4; pr++) {
                        uint32_t addr = stb + boff + pr*16*HPITCH + kc*32;
                        LDSM_X4(bf[pr][0], bf[pr][1], bf[pr][2], bf[pr][3], addr);
                    }
                    #pragma unroll
                    for (int mt = 0; mt < 2; mt++)
                        #pragma unroll
                        for (int nt = 0; nt < 8; nt++)
                            HMMA16816(acc[mt][nt],
                                      af[mt][0], af[mt][1], af[mt][2], af[mt][3],
                                      bf[nt>>1][(nt&1)*2], bf[nt>>1][(nt&1)*2+1]);
                }
            }
        } else {
            #pragma unroll
            for (int kc = 0; kc < 4; kc++) {
                uint32_t af[4][4];
                #pragma unroll
                for (int mt = 0; mt < 4; mt++) {
                    uint32_t addr = stb + aoff + mt*16*HPITCH + kc*32;
                    LDSM_X4(af[mt][0], af[mt][1], af[mt][2], af[mt][3], addr);
                }
                uint32_t bf[4][4];
                #pragma unroll
                for (int pr = 0; pr < 4; pr++) {
                    uint32_t addr = stb + boff + pr*16*HPITCH + kc*32;
                    LDSM_X4(bf[pr][0], bf[pr][1], bf[pr][2], bf[pr][3], addr);
                }
                #pragma unroll
                for (int mt = 0; mt < 4; mt++) {
                    #pragma unroll
                    for (int nt = 0; nt < 8; nt++) {
                        HMMA16816(acc[mt][nt],
                                  af[mt][0], af[mt][1], af[mt][2], af[mt][3],
                                  bf[nt>>1][(nt&1)*2], bf[nt>>1][(nt&1)*2+1]);
                    }
                }
            }
        }
    }

    const int lr = lane >> 2, lc = lane & 3;
    if (tail && wm != 0) return;
    const int mtN = tail ? 2 : 4;
    for (int mt = 0; mt < mtN; mt++) {
        int r0 = m0 + wm*64 + mt*16 + lr;
        #pragma unroll
        for (int nt = 0; nt < 8; nt++) {
            int cc = n0 + wn*64 + nt*8 + lc*2;
            float v0 = acc[mt][nt][0], v1 = acc[mt][nt][1];
            float v2 = acc[mt][nt][2], v3 = acc[mt][nt][3];
            if (bias) {
                float bb0 = bias[cc], bb1 = bias[cc+1];
                v0 += bb0; v1 += bb1; v2 += bb0; v3 += bb1;
            }
            if (RES) {
                if (r0 < M) {
                    float2 rr = *(const float2*)&Rs[(size_t)r0*N + cc];
                    v0 += rr.x; v1 += rr.y;
                }
                if (r0 + 8 < M) {
                    float2 rr = *(const float2*)&Rs[(size_t)(r0+8)*N + cc];
                    v2 += rr.x; v3 += rr.y;
                }
            }
            if (GELU) { v0 = gelu_f(v0); v1 = gelu_f(v1); v2 = gelu_f(v2); v3 = gelu_f(v3); }
            if (sizeof(OutT) == 4) {
                if (r0 < M)     *(float2*)&(((float*)Cp)[(size_t)r0*N + cc])     = make_float2(v0, v1);
                if (r0 + 8 < M) *(float2*)&(((float*)Cp)[(size_t)(r0+8)*N + cc]) = make_float2(v2, v3);
            } else {
                if (r0 < M) {
                    __half2 h = __floats2half2_rn(v0, v1);
                    *(__half2*)&(((__half*)Cp)[(size_t)r0*N + cc]) = h;
                }
                if (r0 + 8 < M) {
                    __half2 h = __floats2half2_rn(v2, v3);
                    *(__half2*)&(((__half*)Cp)[(size_t)(r0+8)*N + cc]) = h;
                }
            }
        }
    }
}

// ---------------------------------------------------------------------------
// SIMT NT SGEMM for the tiny head GEMMs (M=32), fp32
// ---------------------------------------------------------------------------
__global__ void gemm_nt(const float* __restrict__ A, const float* __restrict__ W,
                        const float* __restrict__ bias, float* __restrict__ C,
                        int M, int N, int K) {
    __shared__ float As[16][64];
    __shared__ float Bs[16][64];
    int tid = threadIdx.x;
    int tx = tid & 15, ty = tid >> 4;
    int m0 = blockIdx.y * 64, n0 = blockIdx.x * 64;
    int lr = tid >> 2;
    int lc = (tid & 3) << 2;
    float acc[4][4] = {};
    const float* Aptr = A + (long)(m0 + lr) * K + lc;
    const float* Wptr = W + (long)(n0 + lr) * K + lc;
    bool am = (m0 + lr) < M;
    bool wn = (n0 + lr) < N;
    for (int k0 = 0; k0 < K; k0 += 16) {
        float4 av = am ? *(const float4*)(Aptr + k0) : make_float4(0.f,0.f,0.f,0.f);
        float4 wv = wn ? *(const float4*)(Wptr + k0) : make_float4(0.f,0.f,0.f,0.f);
        As[lc+0][lr]=av.x; As[lc+1][lr]=av.y; As[lc+2][lr]=av.z; As[lc+3][lr]=av.w;
        Bs[lc+0][lr]=wv.x; Bs[lc+1][lr]=wv.y; Bs[lc+2][lr]=wv.z; Bs[lc+3][lr]=wv.w;
        __syncthreads();
        #pragma unroll
        for (int kk = 0; kk < 16; kk++) {
            float4 a = *(const float4*)(&As[kk][ty << 2]);
            float4 b = *(const float4*)(&Bs[kk][tx << 2]);
            acc[0][0] += a.x*b.x; acc[0][1] += a.x*b.y; acc[0][2] += a.x*b.z; acc[0][3] += a.x*b.w;
            acc[1][0] += a.y*b.x; acc[1][1] += a.y*b.y; acc[1][2] += a.y*b.z; acc[1][3] += a.y*b.w;
            acc[2][0] += a.z*b.x; acc[2][1] += a.z*b.y; acc[2][2] += a.z*b.z; acc[2][3] += a.z*b.w;
            acc[3][0] += a.w*b.x; acc[3][1] += a.w*b.y; acc[3][2] += a.w*b.z; acc[3][3] += a.w*b.w;
        }
        __syncthreads();
    }
    #pragma unroll
    for (int i = 0; i < 4; i++) {
        int m = m0 + (ty << 2) + i;
        if (m >= M) continue;
        #pragma unroll
        for (int j = 0; j < 4; j++) {
            int n = n0 + (tx << 2) + j;
            if (n >= N) continue;
            float v = acc[i][j];
            if (bias) v += bias[n];
            C[(long)m * N + n] = v;
        }
    }
}

// ---------------------------------------------------------------------------
// HMMA flash-style attention, 13 warps, one warp per strip (verified R15).
// ---------------------------------------------------------------------------
#define SEQP    208
#define KPITCH  72
#define VPITCH  216
#define PPITCH  216
#define ATTN_T  416
#define ATTN_SMEM ((SEQP*KPITCH + 64*VPITCH + 13*16*PPITCH) * 2)   // 147456

__global__ __launch_bounds__(ATTN_T, 1)
void attn_kernel(const __half* __restrict__ qkv, __half* __restrict__ out, int ns) {
    int b = blockIdx.x / NH, h = blockIdx.x % NH;
    int tid = threadIdx.x, lane = tid & 31, warp = tid >> 5;
    extern __shared__ __half sh[];
    __half* Ks = sh;
    __half* Vt = Ks + SEQP*KPITCH;
    __half* Pw = Vt + 64*VPITCH + warp*16*PPITCH;

    const __half* base = qkv + (size_t)b * NTOK * (3*DD) + h * DH;

    for (int idx = tid; idx < NTOK*8; idx += ATTN_T) {
        int j = idx >> 3, c = idx & 7;
        *(uint4*)&Ks[j*KPITCH + c*8] = *(const uint4*)&base[(size_t)j*(3*DD) + DD + c*8];
    }
    for (int idx = tid; idx < (SEQP-NTOK)*KPITCH; idx += ATTN_T) {
        Ks[(NTOK + idx/KPITCH)*KPITCH + (idx % KPITCH)] = __half(0.0f);
    }
    for (int idx = tid; idx < NTOK*64; idx += ATTN_T) {
        int j = idx >> 6, d = idx & 63;
        Vt[d*VPITCH + j] = base[(size_t)j*(3*DD) + 2*DD + d];
    }
    for (int idx = tid; idx < 64*(VPITCH-NTOK); idx += ATTN_T) {
        int d = idx / (VPITCH-NTOK), c = NTOK + idx % (VPITCH-NTOK);
        Vt[d*VPITCH + c] = __half(0.0f);
    }
    __syncthreads();

    const int s = warp;
    if (s >= ns) return;

    const uint32_t KsB = smem_u32(Ks);
    const uint32_t VtB = smem_u32(Vt);
    const uint32_t PwB = smem_u32(Pw);
    const int lr = lane >> 2, lc = lane & 3;
    const uint32_t browoff = ((lane & 7) + ((lane >> 4) << 3));
    const uint32_t bcol = ((lane >> 3) & 1) * 16;
    const uint32_t aoff = PwB + (uint32_t)(lane & 15) * (PPITCH*2) + (lane >> 4) * 16;

    const int m0 = s * 16;
    #pragma unroll
    for (int t = 0; t < 4; t++) {
        int idx = lane + t*32;
        int r = idx >> 3, c = idx & 7;
        int q = m0 + r;
        uint4 v = make_uint4(0u,0u,0u,0u);
        if (q < NTOK) v = *(const uint4*)&base[(size_t)q*(3*DD) + c*8];
        *(uint4*)&Pw[r*PPITCH + c*8] = v;
    }
    __syncwarp();
    uint32_t af[4][4];
    #pragma unroll
    for (int kc = 0; kc < 4; kc++)
        LDSM_X4(af[kc][0], af[kc][1], af[kc][2], af[kc][3], aoff + kc*32);

    float acc[26][4];
    #pragma unroll
    for (int nt = 0; nt < 26; nt++) {
        acc[nt][0]=0.f; acc[nt][1]=0.f; acc[nt][2]=0.f; acc[nt][3]=0.f;
    }
    #pragma unroll
    for (int kc = 0; kc < 4; kc++) {
        #pragma unroll
        for (int g = 0; g < 13; g++) {
            uint32_t b0,b1,b2,b3;
            LDSM_X4(b0,b1,b2,b3,
                    KsB + (g*16 + browoff)*(KPITCH*2) + bcol + kc*32);
            HMMA16816(acc[2*g  ], af[kc][0],af[kc][1],af[kc][2],af[kc][3], b0, b1);
            HMMA16816(acc[2*g+1], af[kc][0],af[kc][1],af[kc][2],af[kc][3], b2, b3);
        }
    }

    float mx1 = -1e30f, mx2 = -1e30f;
    #pragma unroll
    for (int nt = 0; nt < 26; nt++) {
        #pragma unroll
        for (int e = 0; e < 2; e++) {
            int col = nt*8 + lc*2 + e;
            bool ok = col < NTOK;
            float s1 = ok ? acc[nt][e]   * 0.125f : -1e30f;
            float s2 = ok ? acc[nt][2+e] * 0.125f : -1e30f;
            acc[nt][e] = s1; acc[nt][2+e] = s2;
            mx1 = fmaxf(mx1, s1); mx2 = fmaxf(mx2, s2);
        }
    }
    #pragma unroll
    for (int o = 1; o <= 2; o <<= 1) {
        mx1 = fmaxf(mx1, __shfl_xor_sync(0xffffffffu, mx1, o));
        mx2 = fmaxf(mx2, __shfl_xor_sync(0xffffffffu, mx2, o));
    }
    float sum1 = 0.f, sum2 = 0.f;
    #pragma unroll
    for (int nt = 0; nt < 26; nt++) {
        #pragma unroll
        for (int e = 0; e < 2; e++) {
            float p1 = expf(acc[nt][e]   - mx1);
            float p2 = expf(acc[nt][2+e] - mx2);
            acc[nt][e] = p1; acc[nt][2+e] = p2;
            sum1 += p1; sum2 += p2;
        }
    }
    #pragma unroll
    for (int o = 1; o <= 2; o <<= 1) {
        sum1 += __shfl_xor_sync(0xffffffffu, sum1, o);
        sum2 += __shfl_xor_sync(0xffffffffu, sum2, o);
    }
    #pragma unroll
    for (int nt = 0; nt < 26; nt++) {
        int col = nt*8 + lc*2;
        __half2 p1 = __floats2half2_rn(acc[nt][0], acc[nt][1]);
        __half2 p2 = __floats2half2_rn(acc[nt][2], acc[nt][3]);
        *(__half2*)&Pw[ lr   *PPITCH + col] = p1;
        *(__half2*)&Pw[(lr+8)*PPITCH + col] = p2;
    }
    __syncwarp();

    float oacc[8][4];
    #pragma unroll
    for (int nt = 0; nt < 8; nt++) {
        oacc[nt][0]=0.f; oacc[nt][1]=0.f; oacc[nt][2]=0.f; oacc[nt][3]=0.f;
    }
    for (int kt = 0; kt < 13; kt++) {
        uint32_t pa0,pa1,pa2,pa3;
        LDSM_X4(pa0,pa1,pa2,pa3, aoff + kt*32);
        #pragma unroll
        for (int g = 0; g < 4; g++) {
            uint32_t b0,b1,b2,b3;
            LDSM_X4(b0,b1,b2,b3,
                    VtB + (g*16 + browoff)*(VPITCH*2) + bcol + kt*32);
            HMMA16816(oacc[2*g  ], pa0,pa1,pa2,pa3, b0, b1);
            HMMA16816(oacc[2*g+1], pa0,pa1,pa2,pa3, b2, b3);
        }
    }

    float inv1 = 1.0f / sum1, inv2 = 1.0f / sum2;
    int q1 = m0 + lr, q2 = m0 + lr + 8;
    #pragma unroll
    for (int nt = 0; nt < 8; nt++) {
        int col = nt*8 + lc*2;
        if (q1 < NTOK) {
            __half2 hv = __floats2half2_rn(oacc[nt][0]*inv1, oacc[nt][1]*inv1);
            *(__half2*)&out[((size_t)b*NTOK + q1)*DD + h*DH + col] = hv;
        }
        if (q2 < NTOK) {
            __half2 hv = __floats2half2_rn(oacc[nt][2]*inv2, oacc[nt][3]*inv2);
            *(__half2*)&out[((size_t)b*NTOK + q2)*DD + h*DH + col] = hv;
        }
    }
}

// ---------------------------------------------------------------------------
// host orchestration
// ---------------------------------------------------------------------------
extern "C" void kernel_launch(void* const* d_in, const int* in_sizes, int n_in,
                              void* d_out, int out_size) {
    const float* x_in    = (const float*)d_in[0];
    const float* conv_w  = (const float*)d_in[1];
    const float* cls_tok = (const float*)d_in[2];
    const float* pos     = (const float*)d_in[3];
    const float* lnprew  = (const float*)d_in[4];
    const float* lnpreb  = (const float*)d_in[5];
    const float* ln1w    = (const float*)d_in[6];
    const float* ln1b    = (const float*)d_in[7];
    const float* qkvw    = (const float*)d_in[8];
    const float* qkvb    = (const float*)d_in[9];
    const float* pw      = (const float*)d_in[10];
    const float* pb      = (const float*)d_in[11];
    const float* ln2w    = (const float*)d_in[12];
    const float* ln2b    = (const float*)d_in[13];
    const float* fw      = (const float*)d_in[14];
    const float* fb      = (const float*)d_in[15];
    const float* cw      = (const float*)d_in[16];
    const float* cb      = (const float*)d_in[17];
    const float* lnpostw = (const float*)d_in[18];
    const float* lnpostb = (const float*)d_in[19];
    const float* projw   = (const float*)d_in[20];
    const float* headw   = (const float*)d_in[21];
    const float* headb   = (const float*)d_in[22];

    float  *gx, *gpe, *gc, *gcr, *gcx2, *gcx3, *gz;
    __half *gq, *gh, *go, *gm, *gp, *gca;
    __half *wconv, *wqkv, *wproj, *wfc, *wcpr;
    cudaGetSymbolAddress((void**)&gx,   g_x);
    cudaGetSymbolAddress((void**)&gpe,  g_pe);
    cudaGetSymbolAddress((void**)&gc,   g_cls);
    cudaGetSymbolAddress((void**)&gcr,  g_cr);
    cudaGetSymbolAddress((void**)&gcx2, g_cx2);
    cudaGetSymbolAddress((void**)&gcx3, g_cx3);
    cudaGetSymbolAddress((void**)&gz,   g_z);
    cudaGetSymbolAddress((void**)&gq,   g_qkv);
    cudaGetSymbolAddress((void**)&gh,   g_h);
    cudaGetSymbolAddress((void**)&go,   g_o);
    cudaGetSymbolAddress((void**)&gm,   g_mlp);
    cudaGetSymbolAddress((void**)&gp,   g_pat);
    cudaGetSymbolAddress((void**)&gca,  g_ca);
    cudaGetSymbolAddress((void**)&wconv, g_wconv);
    cudaGetSymbolAddress((void**)&wqkv,  g_wqkv);
    cudaGetSymbolAddress((void**)&wproj, g_wproj);
    cudaGetSymbolAddress((void**)&wfc,   g_wfc);
    cudaGetSymbolAddress((void**)&wcpr,  g_wcpr);

    cudaFuncSetAttribute(attn_kernel, cudaFuncAttributeMaxDynamicSharedMemorySize, ATTN_SMEM);
    cudaFuncSetAttribute(gemm_h<float ,false,false>, cudaFuncAttributeMaxDynamicSharedMemorySize, GH_SMEM);
    cudaFuncSetAttribute(gemm_h<float ,false,true >, cudaFuncAttributeMaxDynamicSharedMemorySize, GH_SMEM);
    cudaFuncSetAttribute(gemm_h<__half,true ,false>, cudaFuncAttributeMaxDynamicSharedMemorySize, GH_SMEM);
    cudaFuncSetAttribute(gemm_h<__half,false,false>, cudaFuncAttributeMaxDynamicSharedMemorySize, GH_SMEM);

    // ---- weight conversion (single launch) ----
    f2h_all_kernel<<<(F2H_C4 + 255)/256, 256>>>(conv_w, wconv, qkvw, wqkv,
                                                pw, wproj, fw, wfc, cw, wcpr);

    const int GY  = MROWS/128 + 1;   // 50 (last block = 32-row tail)
    const int GYP = PROWS/128 + 1;   // 50 (last block = empty tail)

    // ---- patch embed ----
    im2col_kernel<<<(PROWS*DD + 255)/256, 256>>>(x_in);
    gemm_h<float,false,false><<<dim3(DD/256, GYP), 256, GH_SMEM>>>(
        gp, wconv, nullptr, nullptr, gpe, PROWS, DD, DD);
    assemble_ln_kernel<<<MROWS, 256>>>(gpe, cls_tok, pos, lnprew, lnpreb, gx);

    // ---- layers 0..10: full ----
    for (int l = 0; l < DEPTH - 1; l++) {
        ln_warp<__half><<<MROWS/8, 256>>>(gx, gh, ln1w + l*DD, ln1b + l*DD, DD, DD);
        gemm_h<__half,false,false><<<dim3((3*DD)/256, GY), 256, GH_SMEM>>>(
            gh, wqkv + (size_t)l*3*DD*DD, qkvb + (long)l*3*DD, nullptr, gq, MROWS, 3*DD, DD);
        attn_kernel<<<BB*NH, ATTN_T, ATTN_SMEM>>>(gq, go, 13);
        gemm_h<float,false,true><<<dim3(DD/256, GY), 256, GH_SMEM>>>(
            go, wproj + (size_t)l*DD*DD, pb + (long)l*DD, gx, gx, MROWS, DD, DD);
        ln_warp<__half><<<MROWS/8, 256>>>(gx, gh, ln2w + l*DD, ln2b + l*DD, DD, DD);
        gemm_h<__half,true,false><<<dim3(MLPD/256, GY), 256, GH_SMEM>>>(
            gh, wfc + (size_t)l*MLPD*DD, fb + (long)l*MLPD, nullptr, gm, MROWS, MLPD, DD);
        gemm_h<float,false,true><<<dim3(DD/256, GY), 256, GH_SMEM>>>(
            gm, wcpr + (size_t)l*DD*MLPD, cb + (long)l*DD, gx, gx, MROWS, DD, MLPD);
    }

    // ---- layer 11 (last): full ln1/QKV, cls-only attention + MLP ----
    {
        const int l = DEPTH - 1;
        ln_warp<__half><<<MROWS/8, 256>>>(gx, gh, ln1w + l*DD, ln1b + l*DD, DD, DD);
        gemm_h<__half,false,false><<<dim3((3*DD)/256, GY), 256, GH_SMEM>>>(
            gh, wqkv + (size_t)l*3*DD*DD, qkvb + (long)l*3*DD, nullptr, gq, MROWS, 3*DD, DD);
        attn_kernel<<<BB*NH, ATTN_T, ATTN_SMEM>>>(gq, go, 1);   // only cls strip
        gather_cls_kernel<<<(BB*DD + 255)/256, 256>>>(go, gx, gca, gcr);
        gemm_h<float,false,true><<<dim3(DD/256, 1), 256, GH_SMEM>>>(
            gca, wproj + (size_t)l*DD*DD, pb + (long)l*DD, gcr, gcx2, BB, DD, DD);
        ln_warp<__half><<<BB/8, 256>>>(gcx2, gca, ln2w + l*DD, ln2b + l*DD, DD, DD);
        gemm_h<__half,true,false><<<dim3(MLPD/256, 1), 256, GH_SMEM>>>(
            gca, wfc + (size_t)l*MLPD*DD, fb + (long)l*MLPD, nullptr, gm, BB, MLPD, DD);
        gemm_h<float,false,true><<<dim3(DD/256, 1), 256, GH_SMEM>>>(
            gm, wcpr + (size_t)l*DD*MLPD, cb + (long)l*DD, gcx2, gcx3, BB, DD, MLPD);
    }

    // ---- head ----
    ln_warp<float><<<BB/8, 256>>>(gcx3, gc, lnpostw, lnpostb, DD, DD);
    gemm_nt<<<dim3(PROJD/64, 1), 256>>>(gc, projw, nullptr, gz, BB, PROJD, DD);
    gemm_nt<<<dim3((NCLS+63)/64, 1), 256>>>(gz, headw, headb, (float*)d_out, BB, NCLS, PROJD);
}